// round 3
// baseline (speedup 1.0000x reference)
#include <cuda_runtime.h>
#include <cstdint>

#define BATCH 4096
#define TMAX  2048
#define HID   32

typedef unsigned long long ull;

__device__ int g_perm[BATCH];

// ---------------- fast math helpers ----------------
__device__ __forceinline__ float tanh_fast(float x) {
    float y; asm("tanh.approx.f32 %0, %1;" : "=f"(y) : "f"(x)); return y;
}
__device__ __forceinline__ float sigmoid_fast(float x) {
    // sigmoid(x) = 0.5*tanh(0.5x) + 0.5
    return fmaf(0.5f, tanh_fast(0.5f * x), 0.5f);
}
__device__ __forceinline__ float fast_ex2(float x) {
    float y; asm("ex2.approx.f32 %0, %1;" : "=f"(y) : "f"(x)); return y;
}
__device__ __forceinline__ float expf_fast(float x) {
    return fast_ex2(1.4426950408889634f * x);
}
__device__ __forceinline__ void fma2(ull& d, ull a, ull b) {
    asm("fma.rn.f32x2 %0, %1, %2, %0;" : "+l"(d) : "l"(a), "l"(b));
}
__device__ __forceinline__ float hsum2(ull v) {
    float lo = __uint_as_float((unsigned)(v & 0xffffffffu));
    float hi = __uint_as_float((unsigned)(v >> 32));
    return lo + hi;
}

// ---------------- counting sort: longest sequence first ----------------
__global__ void sort_by_len_kernel(const int* __restrict__ lengths) {
    __shared__ int cnt[TMAX];
    __shared__ int tmp[TMAX];
    int tid = threadIdx.x;           // 1024 threads
    for (int i = tid; i < TMAX; i += 1024) cnt[i] = 0;
    __syncthreads();
    for (int i = tid; i < BATCH; i += 1024) {
        int key = TMAX - lengths[i];  // longest first
        atomicAdd(&cnt[key], 1);
    }
    __syncthreads();
    int* src = cnt;
    int* dst = tmp;
    for (int off = 1; off < TMAX; off <<= 1) {
        for (int i = tid; i < TMAX; i += 1024) {
            int v = src[i];
            if (i >= off) v += src[i - off];
            dst[i] = v;
        }
        __syncthreads();
        int* t = src; src = dst; dst = t;
    }
    for (int i = tid; i < TMAX; i += 1024) dst[i] = (i == 0) ? 0 : src[i - 1];
    __syncthreads();
    for (int i = tid; i < BATCH; i += 1024) {
        int key = TMAX - lengths[i];
        int pos = atomicAdd(&dst[key], 1);
        g_perm[pos] = i;
    }
}

// ---- main kernel: one warp per TWO batch elements (weights shared in regs) ----
__global__ void __launch_bounds__(32) bilstm_kernel(
    const float* __restrict__ x,
    const int*   __restrict__ lengths,
    const float* __restrict__ w_ih,
    const float* __restrict__ w_hh,
    const float* __restrict__ b_ih,
    const float* __restrict__ b_hh,
    const float* __restrict__ fc_w,
    const float* __restrict__ fc_b,
    const float* __restrict__ fc2_w,
    const float* __restrict__ fc2_b,
    float* __restrict__ out)
{
    __shared__ __align__(16) float sh[2][2][HID];   // [buffer][element][hid]
    const int lane = threadIdx.x;
    const int b0   = g_perm[2 * blockIdx.x];
    const int b1   = g_perm[2 * blockIdx.x + 1];
    const int L0   = lengths[b0];          // L0 >= L1 (sorted desc)
    const int L1   = lengths[b1];

    // lane j holds w_hh rows j, j+32, j+64, j+96 (i,f,g,o) — shared by both elements
    ull wi[16], wf[16], wg[16], wo[16];
    const ull* W = (const ull*)w_hh;
    #pragma unroll
    for (int p = 0; p < 16; p++) {
        wi[p] = W[(lane      ) * 16 + p];
        wf[p] = W[(lane + 32 ) * 16 + p];
        wg[p] = W[(lane + 64 ) * 16 + p];
        wo[p] = W[(lane + 96 ) * 16 + p];
    }
    const float wih_i = w_ih[lane],      wih_f = w_ih[lane + 32];
    const float wih_g = w_ih[lane + 64], wih_o = w_ih[lane + 96];
    const float bi = b_ih[lane]      + b_hh[lane];
    const float bf = b_ih[lane + 32] + b_hh[lane + 32];
    const float bg = b_ih[lane + 64] + b_hh[lane + 64];
    const float bo = b_ih[lane + 96] + b_hh[lane + 96];

    sh[0][0][lane] = 0.0f; sh[0][1][lane] = 0.0f;
    sh[1][0][lane] = 0.0f; sh[1][1][lane] = 0.0f;
    __syncwarp();

    float c0 = 0.0f, c1 = 0.0f;
    float h0r = 0.0f, h1r = 0.0f;          // own h value kept in register
    int cur = 0;
    const float* xb0 = x + (size_t)b0 * TMAX;
    const float* xb1 = x + (size_t)b1 * TMAX;

    // chunked coalesced prefetch of x: one LDG.32 per lane per 32 steps per element
    int t = L0 - 1;
    int cbase = t & ~31;
    float xcur0  = __ldg(xb0 + cbase + lane);
    float xcur1  = __ldg(xb1 + cbase + lane);
    float xnext0 = (cbase >= 32) ? __ldg(xb0 + cbase - 32 + lane) : 0.0f;
    float xnext1 = (cbase >= 32) ? __ldg(xb1 + cbase - 32 + lane) : 0.0f;

    for (; t >= 0; --t) {
        const float xt0 = __shfl_sync(0xffffffffu, xcur0, t & 31);
        const float xt1 = __shfl_sync(0xffffffffu, xcur1, t & 31);

        const ull* hb0 = (const ull*)sh[cur][0];
        const ull* hb1 = (const ull*)sh[cur][1];
        ull ai0 = 0, af0 = 0, ag0 = 0, ao0 = 0;
        ull ai1 = 0, af1 = 0, ag1 = 0, ao1 = 0;
        #pragma unroll
        for (int p = 0; p < 16; p++) {
            const ull hv0 = hb0[p];
            const ull hv1 = hb1[p];
            fma2(ai0, wi[p], hv0);  fma2(ai1, wi[p], hv1);
            fma2(af0, wf[p], hv0);  fma2(af1, wf[p], hv1);
            fma2(ag0, wg[p], hv0);  fma2(ag1, wg[p], hv1);
            fma2(ao0, wo[p], hv0);  fma2(ao1, wo[p], hv1);
        }

        // element 0 (always active: t < L0)
        {
            const float gi = hsum2(ai0) + fmaf(xt0, wih_i, bi);
            const float gf = hsum2(af0) + fmaf(xt0, wih_f, bf);
            const float gg = hsum2(ag0) + fmaf(xt0, wih_g, bg);
            const float go = hsum2(ao0) + fmaf(xt0, wih_o, bo);
            const float I = sigmoid_fast(gi);
            const float F = sigmoid_fast(gf);
            const float G = tanh_fast(gg);
            const float O = sigmoid_fast(go);
            c0  = fmaf(F, c0, I * G);
            h0r = O * tanh_fast(c0);
        }
        // element 1 (active only while t < L1 — packed-sequence masking)
        {
            const float gi = hsum2(ai1) + fmaf(xt1, wih_i, bi);
            const float gf = hsum2(af1) + fmaf(xt1, wih_f, bf);
            const float gg = hsum2(ag1) + fmaf(xt1, wih_g, bg);
            const float go = hsum2(ao1) + fmaf(xt1, wih_o, bo);
            const float I = sigmoid_fast(gi);
            const float F = sigmoid_fast(gf);
            const float G = tanh_fast(gg);
            const float O = sigmoid_fast(go);
            const float cn = fmaf(F, c1, I * G);
            const float hn = O * tanh_fast(cn);
            const bool act = (t < L1);
            c1  = act ? cn : c1;
            h1r = act ? hn : h1r;
        }

        cur ^= 1;
        sh[cur][0][lane] = h0r;
        sh[cur][1][lane] = h1r;
        __syncwarp();

        if ((t & 31) == 0) {
            xcur0 = xnext0; xcur1 = xnext1;
            cbase -= 32;
            const bool more = (cbase >= 32);
            xnext0 = more ? __ldg(xb0 + cbase - 32 + lane) : 0.0f;
            xnext1 = more ? __ldg(xb1 + cbase - 32 + lane) : 0.0f;
        }
    }

    // ---------------- MLP head for both elements ----------------
    #pragma unroll
    for (int e = 0; e < 2; e++) {
        const float* hfin = sh[cur][e];
        float acc0 = __ldg(fc_b + lane);
        float acc1 = __ldg(fc_b + lane + 32);
        #pragma unroll
        for (int k = 0; k < HID; k++) {
            const float hk = hfin[k];
            acc0 = fmaf(__ldg(fc_w + lane * HID + k),        hk, acc0);
            acc1 = fmaf(__ldg(fc_w + (lane + 32) * HID + k), hk, acc1);
        }
        const float e0 = (acc0 > 0.0f) ? acc0 : (expf_fast(acc0) - 1.0f);
        const float e1 = (acc1 > 0.0f) ? acc1 : (expf_fast(acc1) - 1.0f);
        float p = e0 * __ldg(fc2_w + lane) + e1 * __ldg(fc2_w + lane + 32);
        #pragma unroll
        for (int off = 16; off > 0; off >>= 1)
            p += __shfl_xor_sync(0xffffffffu, p, off);
        if (lane == 0)
            out[e == 0 ? b0 : b1] = sigmoid_fast(p + __ldg(fc2_b));
    }
}

extern "C" void kernel_launch(void* const* d_in, const int* in_sizes, int n_in,
                              void* d_out, int out_size) {
    const float* x     = (const float*)d_in[0];
    const int*   lens  = (const int*)  d_in[1];
    const float* w_ih  = (const float*)d_in[2];
    const float* w_hh  = (const float*)d_in[3];
    const float* b_ih  = (const float*)d_in[4];
    const float* b_hh  = (const float*)d_in[5];
    const float* fc_w  = (const float*)d_in[6];
    const float* fc_b  = (const float*)d_in[7];
    const float* fc2_w = (const float*)d_in[8];
    const float* fc2_b = (const float*)d_in[9];
    float* out = (float*)d_out;

    sort_by_len_kernel<<<1, 1024>>>(lens);
    bilstm_kernel<<<BATCH / 2, 32>>>(x, lens, w_ih, w_hh, b_ih, b_hh,
                                     fc_w, fc_b, fc2_w, fc2_b, out);
}

// round 4
// speedup vs baseline: 1.2566x; 1.2566x over previous
#include <cuda_runtime.h>
#include <cstdint>

#define BATCH 4096
#define TMAX  2048
#define HID   32

typedef unsigned long long ull;

__device__ int g_perm[BATCH];

// ---------------- fast math helpers ----------------
__device__ __forceinline__ float tanh_fast(float x) {
    float y; asm("tanh.approx.f32 %0, %1;" : "=f"(y) : "f"(x)); return y;
}
__device__ __forceinline__ float sigmoid_fast(float x) {
    // sigmoid(x) = 0.5*tanh(0.5x) + 0.5
    return fmaf(0.5f, tanh_fast(0.5f * x), 0.5f);
}
__device__ __forceinline__ float fast_ex2(float x) {
    float y; asm("ex2.approx.f32 %0, %1;" : "=f"(y) : "f"(x)); return y;
}
__device__ __forceinline__ float expf_fast(float x) {
    return fast_ex2(1.4426950408889634f * x);
}
__device__ __forceinline__ void fma2(ull& d, ull a, ull b) {
    asm("fma.rn.f32x2 %0, %1, %2, %0;" : "+l"(d) : "l"(a), "l"(b));
}
__device__ __forceinline__ float hsum2(ull v) {
    float lo = __uint_as_float((unsigned)(v & 0xffffffffu));
    float hi = __uint_as_float((unsigned)(v >> 32));
    return lo + hi;
}
__device__ __forceinline__ ull pack2(float lo, float hi) {
    return (ull)__float_as_uint(lo) | ((ull)__float_as_uint(hi) << 32);
}

// ---------------- counting sort: longest sequence first ----------------
__global__ void sort_by_len_kernel(const int* __restrict__ lengths) {
    __shared__ int cnt[TMAX];
    __shared__ int tmp[TMAX];
    int tid = threadIdx.x;           // 1024 threads
    for (int i = tid; i < TMAX; i += 1024) cnt[i] = 0;
    __syncthreads();
    for (int i = tid; i < BATCH; i += 1024) {
        int key = TMAX - lengths[i];  // longest first
        atomicAdd(&cnt[key], 1);
    }
    __syncthreads();
    int* src = cnt;
    int* dst = tmp;
    for (int off = 1; off < TMAX; off <<= 1) {
        for (int i = tid; i < TMAX; i += 1024) {
            int v = src[i];
            if (i >= off) v += src[i - off];
            dst[i] = v;
        }
        __syncthreads();
        int* t = src; src = dst; dst = t;
    }
    for (int i = tid; i < TMAX; i += 1024) dst[i] = (i == 0) ? 0 : src[i - 1];
    __syncthreads();
    for (int i = tid; i < BATCH; i += 1024) {
        int key = TMAX - lengths[i];
        int pos = atomicAdd(&dst[key], 1);
        g_perm[pos] = i;
    }
}

// one LSTM step; K = position of x within the current 32-wide chunk
#define STEP(K) do {                                                        \
    const float xt = __shfl_sync(0xffffffffu, xcur, (K));                   \
    ull ai = bi2, af = bf2, ag = bg2, ao = bo2;                             \
    const ulonglong2* hb2 = (const ulonglong2*)sh;                          \
    _Pragma("unroll")                                                       \
    for (int p = 0; p < 8; p++) {                                           \
        const ulonglong2 hv = hb2[p];                                       \
        fma2(ai, wi[2*p], hv.x);  fma2(ai, wi[2*p+1], hv.y);                \
        fma2(af, wf[2*p], hv.x);  fma2(af, wf[2*p+1], hv.y);                \
        fma2(ag, wg[2*p], hv.x);  fma2(ag, wg[2*p+1], hv.y);                \
        fma2(ao, wo[2*p], hv.x);  fma2(ao, wo[2*p+1], hv.y);                \
    }                                                                       \
    const float gi = fmaf(xt, wih_i, hsum2(ai));                            \
    const float gf = fmaf(xt, wih_f, hsum2(af));                            \
    const float gg = fmaf(xt, wih_g, hsum2(ag));                            \
    const float go = fmaf(xt, wih_o, hsum2(ao));                            \
    const float I = sigmoid_fast(gi);                                       \
    const float F = sigmoid_fast(gf);                                       \
    const float G = tanh_fast(gg);                                          \
    const float O = sigmoid_fast(go);                                       \
    c = fmaf(F, c, I * G);                                                  \
    sh[lane] = O * tanh_fast(c);                                            \
} while (0)

// ---------------- main kernel: one warp (one CTA of 32) per batch element ----------------
__global__ void __launch_bounds__(32) bilstm_kernel(
    const float* __restrict__ x,
    const int*   __restrict__ lengths,
    const float* __restrict__ w_ih,
    const float* __restrict__ w_hh,
    const float* __restrict__ b_ih,
    const float* __restrict__ b_hh,
    const float* __restrict__ fc_w,
    const float* __restrict__ fc_b,
    const float* __restrict__ fc2_w,
    const float* __restrict__ fc2_b,
    float* __restrict__ out)
{
    __shared__ __align__(16) float sh[HID];
    const int lane = threadIdx.x;
    const int b    = g_perm[blockIdx.x];
    const int L    = lengths[b];

    // lane j holds w_hh rows j, j+32, j+64, j+96 (i,f,g,o), packed f32x2
    ull wi[16], wf[16], wg[16], wo[16];
    const ull* W = (const ull*)w_hh;
    #pragma unroll
    for (int p = 0; p < 16; p++) {
        wi[p] = W[(lane      ) * 16 + p];
        wf[p] = W[(lane + 32 ) * 16 + p];
        wg[p] = W[(lane + 64 ) * 16 + p];
        wo[p] = W[(lane + 96 ) * 16 + p];
    }
    const float wih_i = w_ih[lane],      wih_f = w_ih[lane + 32];
    const float wih_g = w_ih[lane + 64], wih_o = w_ih[lane + 96];
    // biases pre-folded into accumulator init (lo half)
    const ull bi2 = pack2(b_ih[lane]      + b_hh[lane],      0.0f);
    const ull bf2 = pack2(b_ih[lane + 32] + b_hh[lane + 32], 0.0f);
    const ull bg2 = pack2(b_ih[lane + 64] + b_hh[lane + 64], 0.0f);
    const ull bo2 = pack2(b_ih[lane + 96] + b_hh[lane + 96], 0.0f);

    sh[lane] = 0.0f;
    __syncwarp();

    float c = 0.0f;
    const float* xb = x + (size_t)b * TMAX;

    // chunked coalesced x prefetch: one LDG.32 per lane per 32 steps
    int t = L - 1;
    int cbase = t & ~31;
    float xcur  = __ldg(xb + cbase + lane);
    float xnext = (cbase >= 32) ? __ldg(xb + cbase - 32 + lane) : 0.0f;

    // partial (first) chunk: steps t down to cbase, i.e. K = t-cbase .. 0
    for (int k = t - cbase; k >= 0; --k) {
        STEP(k);
    }
    // full chunks of 32, branch-free inner body
    for (cbase -= 32; cbase >= 0; cbase -= 32) {
        xcur  = xnext;
        xnext = (cbase >= 32) ? __ldg(xb + cbase - 32 + lane) : 0.0f;
        #pragma unroll 4
        for (int k = 31; k >= 0; --k) {
            STEP(k);
        }
    }
    __syncwarp();

    // ---------------- MLP head (h replicated through smem) ----------------
    const float* hfin = sh;
    float acc0 = __ldg(fc_b + lane);
    float acc1 = __ldg(fc_b + lane + 32);
    #pragma unroll
    for (int k = 0; k < HID; k++) {
        const float hk = hfin[k];
        acc0 = fmaf(__ldg(fc_w + lane * HID + k),        hk, acc0);
        acc1 = fmaf(__ldg(fc_w + (lane + 32) * HID + k), hk, acc1);
    }
    const float e0 = (acc0 > 0.0f) ? acc0 : (expf_fast(acc0) - 1.0f);
    const float e1 = (acc1 > 0.0f) ? acc1 : (expf_fast(acc1) - 1.0f);
    float p = e0 * __ldg(fc2_w + lane) + e1 * __ldg(fc2_w + lane + 32);
    #pragma unroll
    for (int off = 16; off > 0; off >>= 1)
        p += __shfl_xor_sync(0xffffffffu, p, off);
    if (lane == 0)
        out[b] = sigmoid_fast(p + __ldg(fc2_b));
}

extern "C" void kernel_launch(void* const* d_in, const int* in_sizes, int n_in,
                              void* d_out, int out_size) {
    const float* x     = (const float*)d_in[0];
    const int*   lens  = (const int*)  d_in[1];
    const float* w_ih  = (const float*)d_in[2];
    const float* w_hh  = (const float*)d_in[3];
    const float* b_ih  = (const float*)d_in[4];
    const float* b_hh  = (const float*)d_in[5];
    const float* fc_w  = (const float*)d_in[6];
    const float* fc_b  = (const float*)d_in[7];
    const float* fc2_w = (const float*)d_in[8];
    const float* fc2_b = (const float*)d_in[9];
    float* out = (float*)d_out;

    sort_by_len_kernel<<<1, 1024>>>(lens);
    bilstm_kernel<<<BATCH, 32>>>(x, lens, w_ih, w_hh, b_ih, b_hh,
                                 fc_w, fc_b, fc2_w, fc2_b, out);
}